// round 1
// baseline (speedup 1.0000x reference)
#include <cuda_runtime.h>

#define BB 8
#define LL 512
#define DD 256
#define UU 32
#define SS 16   // query rows per block in the attention kernel

// Device scratch (no allocations allowed): QB = x@Wt + bh, K = x@Wx
__device__ float g_QB[BB * LL * UU];
__device__ float g_K [BB * LL * UU];

__device__ __forceinline__ float tanh_approx(float v) {
    float y;
    asm("tanh.approx.f32 %0, %1;" : "=f"(y) : "f"(v));
    return y;
}

// ---------------------------------------------------------------------------
// Kernel 1: per-row projections. Block handles 4 rows of x (256 floats each).
// Thread o<32 computes QB[row][o], o>=32 computes K[row][o-32].
// ---------------------------------------------------------------------------
__global__ __launch_bounds__(256) void qk_kernel(
    const float* __restrict__ x,
    const float* __restrict__ Wt,
    const float* __restrict__ Wx,
    const float* __restrict__ bh)
{
    __shared__ float xs[4 * DD];
    const int tid  = threadIdx.x;
    const int row0 = blockIdx.x * 4;

    // 4 rows * 256 floats = 1024 floats = 256 float4 -> one float4 per thread
    ((float4*)xs)[tid] = ((const float4*)(x + (size_t)row0 * DD))[tid];
    __syncthreads();

    const int r = tid >> 6;          // 0..3 local row
    const int o = tid & 63;          // 0..63 output selector
    const int u = o & 31;
    const float* __restrict__ W = (o < 32) ? Wt : Wx;
    const float* xr = xs + r * DD;

    float acc = 0.f;
#pragma unroll 8
    for (int d = 0; d < DD; d++)
        acc = fmaf(xr[d], W[d * UU + u], acc);

    const int row = row0 + r;
    if (o < 32) g_QB[row * UU + u] = acc + bh[u];
    else        g_K [row * UU + u] = acc;
}

// ---------------------------------------------------------------------------
// Kernel 2: fused alpha + softmax + AV. One block per (b, 16-query tile).
// ---------------------------------------------------------------------------
__global__ __launch_bounds__(256) void attn_kernel(
    const float* __restrict__ x,
    const float* __restrict__ Wa,
    float* __restrict__ out)
{
    __shared__ float alpha_sm[SS][LL];   // 32 KB
    __shared__ float qb_sm[SS][UU];      // 2 KB
    __shared__ float wa_sm[UU];
    __shared__ float rinv_sm[SS];

    const int tid    = threadIdx.x;
    const int b      = blockIdx.x >> 5;          // L/SS = 32 tiles per batch
    const int s_base = (blockIdx.x & 31) * SS;

    if (tid < UU) wa_sm[tid] = Wa[tid];
    if (tid < (SS * UU) / 4)  // 128 float4 = 512 floats
        ((float4*)qb_sm)[tid] =
            ((const float4*)(g_QB + (size_t)(b * LL + s_base) * UU))[tid];
    __syncthreads();

    // ---- alpha[s][t] = sum_u tanh(qb[s][u] + K[t][u]) * Wa[u] -------------
    for (int half = 0; half < 2; half++) {
        const int t = tid + half * 256;
        const float4* kp  = (const float4*)(g_K + (size_t)(b * LL + t) * UU);
        const float4* wap = (const float4*)wa_sm;

        float acc[SS];
#pragma unroll
        for (int s = 0; s < SS; s++) acc[s] = 0.f;

#pragma unroll 2
        for (int u4 = 0; u4 < UU / 4; u4++) {
            const float4 kq = kp[u4];
            const float4 wq = wap[u4];
            const float kk[4] = {kq.x, kq.y, kq.z, kq.w};
            const float ww[4] = {wq.x, wq.y, wq.z, wq.w};
#pragma unroll
            for (int j = 0; j < 4; j++) {
                const int u = u4 * 4 + j;
#pragma unroll
                for (int s = 0; s < SS; s++)
                    acc[s] = fmaf(tanh_approx(qb_sm[s][u] + kk[j]), ww[j], acc[s]);
            }
        }
#pragma unroll
        for (int s = 0; s < SS; s++) alpha_sm[s][t] = acc[s];
    }
    __syncthreads();

    // ---- softmax over t, one warp per row (8 warps x 2 rows) --------------
    const int warp = tid >> 5, lane = tid & 31;
#pragma unroll
    for (int rr = 0; rr < 2; rr++) {
        const int s = warp + rr * 8;
        float m = -1e30f;
#pragma unroll
        for (int i = 0; i < LL / 32; i++)
            m = fmaxf(m, alpha_sm[s][lane + 32 * i]);
#pragma unroll
        for (int o = 16; o > 0; o >>= 1)
            m = fmaxf(m, __shfl_xor_sync(0xffffffffu, m, o));

        float sum = 0.f;
#pragma unroll
        for (int i = 0; i < LL / 32; i++) {
            const float e = __expf(alpha_sm[s][lane + 32 * i] - m);
            alpha_sm[s][lane + 32 * i] = e;
            sum += e;
        }
#pragma unroll
        for (int o = 16; o > 0; o >>= 1)
            sum += __shfl_xor_sync(0xffffffffu, sum, o);
        if (lane == 0) rinv_sm[s] = 1.0f / sum;
    }
    __syncthreads();

    // ---- AV: out[s][:] = (1/sum_s) * sum_t a[s][t] * x[b][t][:] -----------
    // Thread owns one float4 of D (d4) for 4 consecutive s rows.
    const int s0 = tid >> 6;     // 0..3
    const int d4 = tid & 63;     // 0..63
    const float4* xp = (const float4*)(x + (size_t)b * LL * DD) + d4;

    float4 acc[4];
#pragma unroll
    for (int j = 0; j < 4; j++) acc[j] = make_float4(0.f, 0.f, 0.f, 0.f);

#pragma unroll 4
    for (int t = 0; t < LL; t++) {
        const float4 xv = xp[(size_t)t * (DD / 4)];
#pragma unroll
        for (int j = 0; j < 4; j++) {
            const float a = alpha_sm[s0 * 4 + j][t];
            acc[j].x = fmaf(a, xv.x, acc[j].x);
            acc[j].y = fmaf(a, xv.y, acc[j].y);
            acc[j].z = fmaf(a, xv.z, acc[j].z);
            acc[j].w = fmaf(a, xv.w, acc[j].w);
        }
    }

#pragma unroll
    for (int j = 0; j < 4; j++) {
        const int s = s0 * 4 + j;
        const float r = rinv_sm[s];
        const float4 v = make_float4(acc[j].x * r, acc[j].y * r,
                                     acc[j].z * r, acc[j].w * r);
        ((float4*)(out + (size_t)(b * LL + s_base + s) * DD))[d4] = v;
    }
}

extern "C" void kernel_launch(void* const* d_in, const int* in_sizes, int n_in,
                              void* d_out, int out_size)
{
    const float* x  = (const float*)d_in[0];
    const float* Wt = (const float*)d_in[1];
    const float* Wx = (const float*)d_in[2];
    const float* bh = (const float*)d_in[3];
    const float* Wa = (const float*)d_in[4];
    // d_in[5] = ba: uniform shift per softmax row -> cancels; intentionally unused.
    float* out = (float*)d_out;

    qk_kernel<<<(BB * LL) / 4, 256>>>(x, Wt, Wx, bh);
    attn_kernel<<<BB * (LL / SS), 256>>>(x, Wa, out);
}